// round 15
// baseline (speedup 1.0000x reference)
#include <cuda_runtime.h>
#include <cstdint>

#define N_NODES 8192
#define F_DIM   512
#define H1_DIM  32
#define H2_DIM  16
#define E_NNZ   131072

// ---------------- scratch (static device globals; no allocs) ----------------
__device__ __align__(16) float g_xw0[N_NODES * H1_DIM];   // X @ W0
__device__ __align__(16) float g_h1 [N_NODES * H1_DIM];   // spmm(A, XW0) (pre-relu)
__device__ __align__(16) float g_ah1[N_NODES * H1_DIM];   // spmm(A, relu(h1))
__device__ __align__(16) float g_z  [N_NODES * H2_DIM];   // final latent

// ---------------- helpers -----------------------------------------------------
__device__ __forceinline__ void red_add_v4(float* p, float a, float b, float c, float d) {
    asm volatile("red.global.add.v4.f32 [%0], {%1, %2, %3, %4};"
                 :: "l"(p), "f"(a), "f"(b), "f"(c), "f"(d) : "memory");
}
__device__ __forceinline__ void fma_f32x2(unsigned long long& d,
                                          unsigned long long a,
                                          unsigned long long b) {
    asm("fma.rn.f32x2 %0, %1, %2, %0;" : "+l"(d) : "l"(a), "l"(b));
}
__device__ __forceinline__ unsigned long long pack2(float x, float y) {
    unsigned long long u;
    asm("mov.b64 %0, {%1, %2};" : "=l"(u) : "f"(x), "f"(y));
    return u;
}

// ---------------- K1: XW0 = X @ W0, smem-tiled (32 rows/block, grid 256) -----
__global__ void __launch_bounds__(256) k_xw0(const float* __restrict__ X,
                                             const float* __restrict__ W0) {
    __shared__ float sX [32 * 64];   // [row][k]
    __shared__ float sWp[32 * 64];   // [k_pair][col*2 + parity]
    int tid  = threadIdx.x;
    int wid  = tid >> 5;
    int lane = tid & 31;
    int row0 = blockIdx.x * 32;

    // pre-zero accumulators (32 rows x 32 floats = 256 float4 per buffer)
    {
        float4 z4 = make_float4(0.f, 0.f, 0.f, 0.f);
        reinterpret_cast<float4*>(g_h1  + (size_t)row0 * 32)[tid] = z4;
        reinterpret_cast<float4*>(g_ah1 + (size_t)row0 * 32)[tid] = z4;
    }

    unsigned long long acc[4];
#pragma unroll
    for (int r = 0; r < 4; r++) acc[r] = 0ull;

    for (int k0 = 0; k0 < F_DIM; k0 += 64) {
        __syncthreads();
#pragma unroll
        for (int q = 0; q < 2; q++) {
            int idx = q * 256 + tid;
            int r   = idx >> 4;
            int c4  = idx & 15;
            float4 v = *reinterpret_cast<const float4*>(
                &X[(size_t)(row0 + r) * F_DIM + k0 + c4 * 4]);
            *reinterpret_cast<float4*>(&sX[r * 64 + c4 * 4]) = v;
        }
#pragma unroll
        for (int q = 0; q < 2; q++) {
            int idx = q * 256 + tid;
            int kk  = idx >> 3;
            int c4  = idx & 7;
            float4 v = *reinterpret_cast<const float4*>(
                &W0[(size_t)(k0 + kk) * H1_DIM + c4 * 4]);
            int k2 = kk >> 1, par = kk & 1;
            float* b = &sWp[k2 * 64 + par];
            b[(4 * c4 + 0) * 2] = v.x;
            b[(4 * c4 + 1) * 2] = v.y;
            b[(4 * c4 + 2) * 2] = v.z;
            b[(4 * c4 + 3) * 2] = v.w;
        }
        __syncthreads();

#pragma unroll
        for (int pp = 0; pp < 16; pp++) {
            unsigned long long wa = *reinterpret_cast<const unsigned long long*>(
                &sWp[(2 * pp + 0) * 64 + 2 * lane]);
            unsigned long long wb = *reinterpret_cast<const unsigned long long*>(
                &sWp[(2 * pp + 1) * 64 + 2 * lane]);
#pragma unroll
            for (int r = 0; r < 4; r++) {
                float4 xv = *reinterpret_cast<const float4*>(
                    &sX[(wid * 4 + r) * 64 + 4 * pp]);
                fma_f32x2(acc[r], pack2(xv.x, xv.y), wa);
                fma_f32x2(acc[r], pack2(xv.z, xv.w), wb);
            }
        }
    }

#pragma unroll
    for (int r = 0; r < 4; r++) {
        unsigned long long u = acc[r];
        float lo = __int_as_float((int)(u & 0xffffffffull));
        float hi = __int_as_float((int)(u >> 32));
        g_xw0[(size_t)(row0 + wid * 4 + r) * H1_DIM + lane] = lo + hi;
    }
}

// ---------------- K2: h1 = spmm(A, XW0)  (4 edges/thread, 8 thr/edge) ------
// Edge targets are independent random rows -> the 4 red.v4 ops do NOT
// serialize on one L2 address (unlike R6's same-row split).
__global__ void k_spmm1(const int* __restrict__ rows, const int* __restrict__ cols,
                        const float* __restrict__ vals) {
    unsigned t = blockIdx.x * blockDim.x + threadIdx.x;    // < (E/4)*8
    unsigned e0 = t >> 3;              // 0 .. E/4-1
    unsigned s  = t & 7;

    int   r[4], c[4];
    float v[4];
#pragma unroll
    for (int q = 0; q < 4; q++) {
        unsigned e = e0 + q * (E_NNZ / 4);
        r[q] = rows[e];
        c[q] = cols[e];
        v[q] = vals[e];
    }
    float4 x[4];
#pragma unroll
    for (int q = 0; q < 4; q++)
        x[q] = *reinterpret_cast<const float4*>(&g_xw0[c[q] * H1_DIM + s * 4]);
#pragma unroll
    for (int q = 0; q < 4; q++)
        red_add_v4(&g_h1[r[q] * H1_DIM + s * 4],
                   v[q] * x[q].x, v[q] * x[q].y, v[q] * x[q].z, v[q] * x[q].w);
}

// ---------------- K3: ah1 = spmm(A, relu(h1))  (4 edges/thread) ------------
__global__ void k_spmm2(const int* __restrict__ rows, const int* __restrict__ cols,
                        const float* __restrict__ vals) {
    unsigned t = blockIdx.x * blockDim.x + threadIdx.x;    // < (E/4)*8
    unsigned e0 = t >> 3;
    unsigned s  = t & 7;

    int   r[4], c[4];
    float v[4];
#pragma unroll
    for (int q = 0; q < 4; q++) {
        unsigned e = e0 + q * (E_NNZ / 4);
        r[q] = rows[e];
        c[q] = cols[e];
        v[q] = vals[e];
    }
    float4 x[4];
#pragma unroll
    for (int q = 0; q < 4; q++)
        x[q] = *reinterpret_cast<const float4*>(&g_h1[c[q] * H1_DIM + s * 4]);
#pragma unroll
    for (int q = 0; q < 4; q++)
        red_add_v4(&g_ah1[r[q] * H1_DIM + s * 4],
                   v[q] * fmaxf(x[q].x, 0.f), v[q] * fmaxf(x[q].y, 0.f),
                   v[q] * fmaxf(x[q].z, 0.f), v[q] * fmaxf(x[q].w, 0.f));
}

// ---------------- K4: fused heads: t = ah1@[W1|W2|W3], softmax, reparam ----
// Valid because spmm(A, h1@Wk) == (spmm(A, h1))@Wk  (associativity).
// Measured-optimal shape: 512-thread blocks, 32 rows each, grid 256.
__global__ void __launch_bounds__(512) k_fuse(
        const float* __restrict__ W1, const float* __restrict__ W2,
        const float* __restrict__ W3,
        const float* __restrict__ s1, const float* __restrict__ s2) {
    __shared__ float sW[32 * 48];
    __shared__ float srow[32 * 32];
    int tid = threadIdx.x;
    {
        int i = tid;          // 0..511 covers all 512 weight elems per matrix
        int k = i >> 4, j = i & 15;
        sW[k * 48 + j]      = W1[i];
        sW[k * 48 + 16 + j] = W2[i];
        sW[k * 48 + 32 + j] = W3[i];
    }
    int row0 = blockIdx.x * 32;
    if (tid < 256) {
        int r  = tid >> 3;
        int c4 = (tid & 7) * 4;
        *reinterpret_cast<float4*>(&srow[r * 32 + c4]) =
            *reinterpret_cast<const float4*>(&g_ah1[(size_t)(row0 + r) * 32 + c4]);
    }
    __syncthreads();

    int rr = tid >> 4;     // local row 0..31
    int l  = tid & 15;     // output col 0..15
    float a1 = 0.f, a2 = 0.f, a3 = 0.f;
#pragma unroll
    for (int k = 0; k < 32; k++) {
        float v = srow[rr * 32 + k];
        a1 = fmaf(v, sW[k * 48 + l],      a1);
        a2 = fmaf(v, sW[k * 48 + 16 + l], a2);
        a3 = fmaf(v, sW[k * 48 + 32 + l], a3);
    }

    float m2 = a2, m3 = a3;
#pragma unroll
    for (int d = 8; d; d >>= 1) {
        m2 = fmaxf(m2, __shfl_xor_sync(0xffffffffu, m2, d));
        m3 = fmaxf(m3, __shfl_xor_sync(0xffffffffu, m3, d));
    }
    float e2 = __expf(a2 - m2), e3 = __expf(a3 - m3);
    float q2 = e2, q3 = e3;
#pragma unroll
    for (int d = 8; d; d >>= 1) {
        q2 += __shfl_xor_sync(0xffffffffu, q2, d);
        q3 += __shfl_xor_sync(0xffffffffu, q3, d);
    }
    float p2 = __fdividef(e2, q2);          // z_log_en
    float p3 = __fdividef(e3, q3);          // z_log_he
    int row = row0 + rr;
    float z_enn = __expf(p2) + s1[row * 16 + l] * (0.1f * __expf(p3));
    g_z[row * 16 + l] = a1 + s2[row * 16 + l] * z_enn;
}

// ---------------- K6: out = z @ z^T, 128x32 tiles, occ=4, __stcs stores ----
#define ZPAD   18
#define SM_STR 132    // 33 vecs
#define ZZT_SMEM_BYTES (32 * SM_STR * 4)   // 16896; compute phase needs 11520

__global__ void __launch_bounds__(256, 4) k_zzt(float* __restrict__ out) {
    extern __shared__ float sm[];
    float* szi  = sm;                       // [128][ZPAD] (compute phase)
    float* szj  = sm + 128 * ZPAD;          // [32][ZPAD]
    float* sm_m = sm;                       // [32][SM_STR] (staging, overlaps)

    // block -> (lower-tri square tile l, quarter h)
    int bx = blockIdx.x;
    int l  = bx >> 2;
    int h  = bx & 3;
    float f = sqrtf(8.0f * (float)l + 1.0f);
    int bi = (int)((f - 1.0f) * 0.5f);
    while ((bi + 1) * (bi + 2) / 2 <= l) bi++;
    while (bi * (bi + 1) / 2 > l) bi--;
    int bj = l - bi * (bi + 1) / 2;

    int i0 = bi * 128;
    int j0 = bj * 128 + h * 32;
    int tid = threadIdx.x;

    // load z tiles: szi 128x16 (512 float4, 2/thread); szj 32x16 (128 float4)
#pragma unroll
    for (int q = 0; q < 2; q++) {
        int idx = q * 256 + tid;
        int r = idx >> 2;
        int c = (idx & 3) * 4;
        float4 vi = *reinterpret_cast<const float4*>(&g_z[(i0 + r) * 16 + c]);
        *reinterpret_cast<float2*>(&szi[r * ZPAD + c])     = make_float2(vi.x, vi.y);
        *reinterpret_cast<float2*>(&szi[r * ZPAD + c + 2]) = make_float2(vi.z, vi.w);
    }
    if (tid < 128) {
        int r = tid >> 2;
        int c = (tid & 3) * 4;
        float4 vj = *reinterpret_cast<const float4*>(&g_z[(j0 + r) * 16 + c]);
        *reinterpret_cast<float2*>(&szj[r * ZPAD + c])     = make_float2(vj.x, vj.y);
        *reinterpret_cast<float2*>(&szj[r * ZPAD + c + 2]) = make_float2(vj.z, vj.w);
    }
    __syncthreads();

    int ti = tid >> 4;    // 0..15 : rows ti+16r (r<8)
    int tj = tid & 15;    // 0..15 : cols tj+16c (c<2)

    unsigned long long acc[8][2];
#pragma unroll
    for (int r = 0; r < 8; r++)
#pragma unroll
        for (int c = 0; c < 2; c++) acc[r][c] = 0ull;

#pragma unroll
    for (int kp = 0; kp < 8; kp++) {
        unsigned long long a[8], b[2];
#pragma unroll
        for (int r = 0; r < 8; r++)
            a[r] = *reinterpret_cast<const unsigned long long*>(
                &szi[(ti + 16 * r) * ZPAD + 2 * kp]);
#pragma unroll
        for (int c = 0; c < 2; c++)
            b[c] = *reinterpret_cast<const unsigned long long*>(
                &szj[(tj + 16 * c) * ZPAD + 2 * kp]);
#pragma unroll
        for (int r = 0; r < 8; r++)
#pragma unroll
            for (int c = 0; c < 2; c++) fma_f32x2(acc[r][c], a[r], b[c]);
    }

    bool mirror = (bi != bj);

    // finalize; store direct tile straight from registers (streaming)
    float res[8][2];
#pragma unroll
    for (int r = 0; r < 8; r++)
#pragma unroll
        for (int c = 0; c < 2; c++) {
            unsigned long long u = acc[r][c];
            float lo = __int_as_float((int)(u & 0xffffffffull));
            float hi = __int_as_float((int)(u >> 32));
            res[r][c] = lo + hi;
            __stcs(&out[(size_t)(i0 + ti + 16 * r) * N_NODES + j0 + tj + 16 * c],
                   res[r][c]);
        }

    // mirror tile via smem transpose staging
    if (mirror) {
        __syncthreads();    // compute-phase smem reads done before overwrite
#pragma unroll
        for (int r = 0; r < 8; r++)
#pragma unroll
            for (int c = 0; c < 2; c++)
                sm_m[(tj + 16 * c) * SM_STR + ti + 16 * r] = res[r][c];
        __syncthreads();

        int lane = tid & 31;
        int w    = tid >> 5;   // 0..7, warp handles rows 4w..4w+3
#pragma unroll
        for (int m = 0; m < 4; m++) {
            int j = 4 * w + m;
            float4 v = *reinterpret_cast<const float4*>(&sm_m[j * SM_STR + 4 * lane]);
            __stcs(reinterpret_cast<float4*>(
                       &out[(size_t)(j0 + j) * N_NODES + i0 + 4 * lane]), v);
        }
    }
}

// ---------------- launcher ---------------------------------------------------
extern "C" void kernel_launch(void* const* d_in, const int* in_sizes, int n_in,
                              void* d_out, int out_size) {
    const float* features = (const float*)d_in[0];
    const int*   adj_rows = (const int*)  d_in[1];
    const int*   adj_cols = (const int*)  d_in[2];
    const float* adj_val  = (const float*)d_in[3];
    const float* W0       = (const float*)d_in[4];
    const float* W1       = (const float*)d_in[5];
    const float* W2       = (const float*)d_in[6];
    const float* W3       = (const float*)d_in[7];
    const float* sample_1 = (const float*)d_in[8];
    const float* sample_2 = (const float*)d_in[9];
    float* out = (float*)d_out;

    cudaFuncSetAttribute(k_zzt, cudaFuncAttributeMaxDynamicSharedMemorySize,
                         ZZT_SMEM_BYTES);

    k_xw0  <<<N_NODES / 32, 256>>>(features, W0);
    k_spmm1<<<E_NNZ * 2 / 256, 256>>>(adj_rows, adj_cols, adj_val);
    k_spmm2<<<E_NNZ * 2 / 256, 256>>>(adj_rows, adj_cols, adj_val);
    k_fuse <<<N_NODES / 32, 512>>>(W1, W2, W3, sample_1, sample_2);

    int ntiles = (N_NODES / 128) * (N_NODES / 128 + 1) / 2;   // 2080
    k_zzt<<<ntiles * 4, 256, ZZT_SMEM_BYTES>>>(out);
}

// round 16
// speedup vs baseline: 1.0212x; 1.0212x over previous
#include <cuda_runtime.h>
#include <cstdint>

#define N_NODES 8192
#define F_DIM   512
#define H1_DIM  32
#define H2_DIM  16
#define E_NNZ   131072

// ---------------- scratch (static device globals; no allocs) ----------------
__device__ __align__(16) float g_xw0[N_NODES * H1_DIM];   // X @ W0
__device__ __align__(16) float g_h1 [N_NODES * H1_DIM];   // spmm(A, XW0) (pre-relu)
__device__ __align__(16) float g_ah1[N_NODES * H1_DIM];   // spmm(A, relu(h1))
__device__ __align__(16) float g_z  [N_NODES * H2_DIM];   // final latent

// ---------------- helpers -----------------------------------------------------
__device__ __forceinline__ void red_add_v4(float* p, float a, float b, float c, float d) {
    asm volatile("red.global.add.v4.f32 [%0], {%1, %2, %3, %4};"
                 :: "l"(p), "f"(a), "f"(b), "f"(c), "f"(d) : "memory");
}
__device__ __forceinline__ void fma_f32x2(unsigned long long& d,
                                          unsigned long long a,
                                          unsigned long long b) {
    asm("fma.rn.f32x2 %0, %1, %2, %0;" : "+l"(d) : "l"(a), "l"(b));
}
__device__ __forceinline__ unsigned long long pack2(float x, float y) {
    unsigned long long u;
    asm("mov.b64 %0, {%1, %2};" : "=l"(u) : "f"(x), "f"(y));
    return u;
}

// ---------------- K1: XW0 = X @ W0, smem-tiled (32 rows/block, grid 256) -----
__global__ void __launch_bounds__(256) k_xw0(const float* __restrict__ X,
                                             const float* __restrict__ W0) {
    __shared__ float sX [32 * 64];   // [row][k]
    __shared__ float sWp[32 * 64];   // [k_pair][col*2 + parity]
    int tid  = threadIdx.x;
    int wid  = tid >> 5;
    int lane = tid & 31;
    int row0 = blockIdx.x * 32;

    // pre-zero accumulators (32 rows x 32 floats = 256 float4 per buffer)
    {
        float4 z4 = make_float4(0.f, 0.f, 0.f, 0.f);
        reinterpret_cast<float4*>(g_h1  + (size_t)row0 * 32)[tid] = z4;
        reinterpret_cast<float4*>(g_ah1 + (size_t)row0 * 32)[tid] = z4;
    }

    unsigned long long acc[4];
#pragma unroll
    for (int r = 0; r < 4; r++) acc[r] = 0ull;

    for (int k0 = 0; k0 < F_DIM; k0 += 64) {
        __syncthreads();
#pragma unroll
        for (int q = 0; q < 2; q++) {
            int idx = q * 256 + tid;
            int r   = idx >> 4;
            int c4  = idx & 15;
            float4 v = *reinterpret_cast<const float4*>(
                &X[(size_t)(row0 + r) * F_DIM + k0 + c4 * 4]);
            *reinterpret_cast<float4*>(&sX[r * 64 + c4 * 4]) = v;
        }
#pragma unroll
        for (int q = 0; q < 2; q++) {
            int idx = q * 256 + tid;
            int kk  = idx >> 3;
            int c4  = idx & 7;
            float4 v = *reinterpret_cast<const float4*>(
                &W0[(size_t)(k0 + kk) * H1_DIM + c4 * 4]);
            int k2 = kk >> 1, par = kk & 1;
            float* b = &sWp[k2 * 64 + par];
            b[(4 * c4 + 0) * 2] = v.x;
            b[(4 * c4 + 1) * 2] = v.y;
            b[(4 * c4 + 2) * 2] = v.z;
            b[(4 * c4 + 3) * 2] = v.w;
        }
        __syncthreads();

#pragma unroll
        for (int pp = 0; pp < 16; pp++) {
            unsigned long long wa = *reinterpret_cast<const unsigned long long*>(
                &sWp[(2 * pp + 0) * 64 + 2 * lane]);
            unsigned long long wb = *reinterpret_cast<const unsigned long long*>(
                &sWp[(2 * pp + 1) * 64 + 2 * lane]);
#pragma unroll
            for (int r = 0; r < 4; r++) {
                float4 xv = *reinterpret_cast<const float4*>(
                    &sX[(wid * 4 + r) * 64 + 4 * pp]);
                fma_f32x2(acc[r], pack2(xv.x, xv.y), wa);
                fma_f32x2(acc[r], pack2(xv.z, xv.w), wb);
            }
        }
    }

#pragma unroll
    for (int r = 0; r < 4; r++) {
        unsigned long long u = acc[r];
        float lo = __int_as_float((int)(u & 0xffffffffull));
        float hi = __int_as_float((int)(u >> 32));
        g_xw0[(size_t)(row0 + wid * 4 + r) * H1_DIM + lane] = lo + hi;
    }
}

// ---------------- K2: h1 = spmm(A, XW0)  (2 edges/thread, 8 thr/edge) ------
// PDL: index/value loads (pure inputs) issued BEFORE the grid-dependency
// sync; the gather from g_xw0 only after.
__global__ void k_spmm1(const int* __restrict__ rows, const int* __restrict__ cols,
                        const float* __restrict__ vals) {
    unsigned t = blockIdx.x * blockDim.x + threadIdx.x;    // < (E/2)*8
    unsigned e = t >> 3;
    unsigned s = t & 7;
    unsigned e2 = e + E_NNZ / 2;

    int   r1 = rows[e],  c1 = cols[e];
    float v1 = vals[e];
    int   r2 = rows[e2], c2 = cols[e2];
    float v2 = vals[e2];

    cudaGridDependencySynchronize();

    float4 x1 = *reinterpret_cast<const float4*>(&g_xw0[c1 * H1_DIM + s * 4]);
    float4 x2 = *reinterpret_cast<const float4*>(&g_xw0[c2 * H1_DIM + s * 4]);
    red_add_v4(&g_h1[r1 * H1_DIM + s * 4], v1 * x1.x, v1 * x1.y, v1 * x1.z, v1 * x1.w);
    red_add_v4(&g_h1[r2 * H1_DIM + s * 4], v2 * x2.x, v2 * x2.y, v2 * x2.z, v2 * x2.w);
}

// ---------------- K3: ah1 = spmm(A, relu(h1))  (2 edges/thread, PDL) -------
__global__ void k_spmm2(const int* __restrict__ rows, const int* __restrict__ cols,
                        const float* __restrict__ vals) {
    unsigned t = blockIdx.x * blockDim.x + threadIdx.x;    // < (E/2)*8
    unsigned e = t >> 3;
    unsigned s = t & 7;
    unsigned e2 = e + E_NNZ / 2;

    int   r1 = rows[e],  c1 = cols[e];
    float v1 = vals[e];
    int   r2 = rows[e2], c2 = cols[e2];
    float v2 = vals[e2];

    cudaGridDependencySynchronize();

    float4 x1 = *reinterpret_cast<const float4*>(&g_h1[c1 * H1_DIM + s * 4]);
    float4 x2 = *reinterpret_cast<const float4*>(&g_h1[c2 * H1_DIM + s * 4]);
    red_add_v4(&g_ah1[r1 * H1_DIM + s * 4],
               v1 * fmaxf(x1.x, 0.f), v1 * fmaxf(x1.y, 0.f),
               v1 * fmaxf(x1.z, 0.f), v1 * fmaxf(x1.w, 0.f));
    red_add_v4(&g_ah1[r2 * H1_DIM + s * 4],
               v2 * fmaxf(x2.x, 0.f), v2 * fmaxf(x2.y, 0.f),
               v2 * fmaxf(x2.z, 0.f), v2 * fmaxf(x2.w, 0.f));
}

// ---------------- K4: fused heads (PDL): weights + samples prefetched ------
// Valid because spmm(A, h1@Wk) == (spmm(A, h1))@Wk  (associativity).
__global__ void __launch_bounds__(512) k_fuse(
        const float* __restrict__ W1, const float* __restrict__ W2,
        const float* __restrict__ W3,
        const float* __restrict__ s1, const float* __restrict__ s2) {
    __shared__ float sW[32 * 48];
    __shared__ float srow[32 * 32];
    int tid = threadIdx.x;
    int row0 = blockIdx.x * 32;
    int rr = tid >> 4;     // local row 0..31
    int l  = tid & 15;     // output col 0..15
    int row = row0 + rr;

    // pure-input prefetches (legal pre-sync under PDL)
    float s1v = s1[row * 16 + l];
    float s2v = s2[row * 16 + l];
    {
        int i = tid;          // 0..511 covers all 512 weight elems per matrix
        int k = i >> 4, j = i & 15;
        sW[k * 48 + j]      = W1[i];
        sW[k * 48 + 16 + j] = W2[i];
        sW[k * 48 + 32 + j] = W3[i];
    }

    cudaGridDependencySynchronize();

    if (tid < 256) {
        int r  = tid >> 3;
        int c4 = (tid & 7) * 4;
        *reinterpret_cast<float4*>(&srow[r * 32 + c4]) =
            *reinterpret_cast<const float4*>(&g_ah1[(size_t)(row0 + r) * 32 + c4]);
    }
    __syncthreads();

    float a1 = 0.f, a2 = 0.f, a3 = 0.f;
#pragma unroll
    for (int k = 0; k < 32; k++) {
        float v = srow[rr * 32 + k];
        a1 = fmaf(v, sW[k * 48 + l],      a1);
        a2 = fmaf(v, sW[k * 48 + 16 + l], a2);
        a3 = fmaf(v, sW[k * 48 + 32 + l], a3);
    }

    float m2 = a2, m3 = a3;
#pragma unroll
    for (int d = 8; d; d >>= 1) {
        m2 = fmaxf(m2, __shfl_xor_sync(0xffffffffu, m2, d));
        m3 = fmaxf(m3, __shfl_xor_sync(0xffffffffu, m3, d));
    }
    float e2 = __expf(a2 - m2), e3 = __expf(a3 - m3);
    float q2 = e2, q3 = e3;
#pragma unroll
    for (int d = 8; d; d >>= 1) {
        q2 += __shfl_xor_sync(0xffffffffu, q2, d);
        q3 += __shfl_xor_sync(0xffffffffu, q3, d);
    }
    float p2 = __fdividef(e2, q2);          // z_log_en
    float p3 = __fdividef(e3, q3);          // z_log_he
    float z_enn = __expf(p2) + s1v * (0.1f * __expf(p3));
    g_z[row * 16 + l] = a1 + s2v * z_enn;
}

// ---------------- K6: out = z @ z^T, 128x32 tiles, occ=4, __stcs, PDL ------
#define ZPAD   18
#define SM_STR 132    // 33 vecs
#define ZZT_SMEM_BYTES (32 * SM_STR * 4)   // 16896; compute phase needs 11520

__global__ void __launch_bounds__(256, 4) k_zzt(float* __restrict__ out) {
    extern __shared__ float sm[];
    float* szi  = sm;                       // [128][ZPAD] (compute phase)
    float* szj  = sm + 128 * ZPAD;          // [32][ZPAD]
    float* sm_m = sm;                       // [32][SM_STR] (staging, overlaps)

    // block -> (lower-tri square tile l, quarter h)  (pure index math pre-sync)
    int bx = blockIdx.x;
    int l  = bx >> 2;
    int h  = bx & 3;
    float f = sqrtf(8.0f * (float)l + 1.0f);
    int bi = (int)((f - 1.0f) * 0.5f);
    while ((bi + 1) * (bi + 2) / 2 <= l) bi++;
    while (bi * (bi + 1) / 2 > l) bi--;
    int bj = l - bi * (bi + 1) / 2;

    int i0 = bi * 128;
    int j0 = bj * 128 + h * 32;
    int tid = threadIdx.x;

    cudaGridDependencySynchronize();

    // load z tiles: szi 128x16 (512 float4, 2/thread); szj 32x16 (128 float4)
#pragma unroll
    for (int q = 0; q < 2; q++) {
        int idx = q * 256 + tid;
        int r = idx >> 2;
        int c = (idx & 3) * 4;
        float4 vi = *reinterpret_cast<const float4*>(&g_z[(i0 + r) * 16 + c]);
        *reinterpret_cast<float2*>(&szi[r * ZPAD + c])     = make_float2(vi.x, vi.y);
        *reinterpret_cast<float2*>(&szi[r * ZPAD + c + 2]) = make_float2(vi.z, vi.w);
    }
    if (tid < 128) {
        int r = tid >> 2;
        int c = (tid & 3) * 4;
        float4 vj = *reinterpret_cast<const float4*>(&g_z[(j0 + r) * 16 + c]);
        *reinterpret_cast<float2*>(&szj[r * ZPAD + c])     = make_float2(vj.x, vj.y);
        *reinterpret_cast<float2*>(&szj[r * ZPAD + c + 2]) = make_float2(vj.z, vj.w);
    }
    __syncthreads();

    int ti = tid >> 4;    // 0..15 : rows ti+16r (r<8)
    int tj = tid & 15;    // 0..15 : cols tj+16c (c<2)

    unsigned long long acc[8][2];
#pragma unroll
    for (int r = 0; r < 8; r++)
#pragma unroll
        for (int c = 0; c < 2; c++) acc[r][c] = 0ull;

#pragma unroll
    for (int kp = 0; kp < 8; kp++) {
        unsigned long long a[8], b[2];
#pragma unroll
        for (int r = 0; r < 8; r++)
            a[r] = *reinterpret_cast<const unsigned long long*>(
                &szi[(ti + 16 * r) * ZPAD + 2 * kp]);
#pragma unroll
        for (int c = 0; c < 2; c++)
            b[c] = *reinterpret_cast<const unsigned long long*>(
                &szj[(tj + 16 * c) * ZPAD + 2 * kp]);
#pragma unroll
        for (int r = 0; r < 8; r++)
#pragma unroll
            for (int c = 0; c < 2; c++) fma_f32x2(acc[r][c], a[r], b[c]);
    }

    bool mirror = (bi != bj);

    // finalize; store direct tile straight from registers (streaming)
    float res[8][2];
#pragma unroll
    for (int r = 0; r < 8; r++)
#pragma unroll
        for (int c = 0; c < 2; c++) {
            unsigned long long u = acc[r][c];
            float lo = __int_as_float((int)(u & 0xffffffffull));
            float hi = __int_as_float((int)(u >> 32));
            res[r][c] = lo + hi;
            __stcs(&out[(size_t)(i0 + ti + 16 * r) * N_NODES + j0 + tj + 16 * c],
                   res[r][c]);
        }

    // mirror tile via smem transpose staging
    if (mirror) {
        __syncthreads();    // compute-phase smem reads done before overwrite
#pragma unroll
        for (int r = 0; r < 8; r++)
#pragma unroll
            for (int c = 0; c < 2; c++)
                sm_m[(tj + 16 * c) * SM_STR + ti + 16 * r] = res[r][c];
        __syncthreads();

        int lane = tid & 31;
        int w    = tid >> 5;   // 0..7, warp handles rows 4w..4w+3
#pragma unroll
        for (int m = 0; m < 4; m++) {
            int j = 4 * w + m;
            float4 v = *reinterpret_cast<const float4*>(&sm_m[j * SM_STR + 4 * lane]);
            __stcs(reinterpret_cast<float4*>(
                       &out[(size_t)(j0 + j) * N_NODES + i0 + 4 * lane]), v);
        }
    }
}

// ---------------- launcher ---------------------------------------------------
template <typename K, typename... Args>
static void launch_pdl(K kernel, dim3 grid, dim3 block, size_t smem, Args... args) {
    cudaLaunchConfig_t cfg = {};
    cfg.gridDim = grid;
    cfg.blockDim = block;
    cfg.dynamicSmemBytes = smem;
    cfg.stream = 0;
    cudaLaunchAttribute attr[1];
    attr[0].id = cudaLaunchAttributeProgrammaticStreamSerialization;
    attr[0].val.programmaticStreamSerializationAllowed = 1;
    cfg.attrs = attr;
    cfg.numAttrs = 1;
    cudaLaunchKernelEx(&cfg, kernel, args...);
}

extern "C" void kernel_launch(void* const* d_in, const int* in_sizes, int n_in,
                              void* d_out, int out_size) {
    const float* features = (const float*)d_in[0];
    const int*   adj_rows = (const int*)  d_in[1];
    const int*   adj_cols = (const int*)  d_in[2];
    const float* adj_val  = (const float*)d_in[3];
    const float* W0       = (const float*)d_in[4];
    const float* W1       = (const float*)d_in[5];
    const float* W2       = (const float*)d_in[6];
    const float* W3       = (const float*)d_in[7];
    const float* sample_1 = (const float*)d_in[8];
    const float* sample_2 = (const float*)d_in[9];
    float* out = (float*)d_out;

    cudaFuncSetAttribute(k_zzt, cudaFuncAttributeMaxDynamicSharedMemorySize,
                         ZZT_SMEM_BYTES);

    k_xw0<<<N_NODES / 32, 256>>>(features, W0);
    launch_pdl(k_spmm1, dim3(E_NNZ * 4 / 256), dim3(256), 0,
               adj_rows, adj_cols, adj_val);
    launch_pdl(k_spmm2, dim3(E_NNZ * 4 / 256), dim3(256), 0,
               adj_rows, adj_cols, adj_val);
    launch_pdl(k_fuse, dim3(N_NODES / 32), dim3(512), 0,
               W1, W2, W3, sample_1, sample_2);

    int ntiles = (N_NODES / 128) * (N_NODES / 128 + 1) / 2;   // 2080
    launch_pdl(k_zzt, dim3(ntiles * 4), dim3(256), (size_t)ZZT_SMEM_BYTES, out);
}